// round 2
// baseline (speedup 1.0000x reference)
#include <cuda_runtime.h>
#include <math.h>
#include <stdint.h>

// ---------------------------------------------------------------------------
// SingleToPairwise — fp32 baseline, decomposed pipeline
//   pool+gelu -> SGEMM(qk) -> SGEMM(rel_enc, rows 544..1567 only)
//   -> SGEMM(outer) -> batched SGEMM t_q/t_k (per head) -> batched SGEMM sim
//   -> transpose t to [i][p][h] -> fused gather + pair-projection + outer sum
// ---------------------------------------------------------------------------

// scratch (device globals: allocation-free)
__device__ float g_pooled[1024 * 768];
__device__ float g_gelu[1024 * 768];
__device__ float g_qk[1024 * 8192];          // [i][ q(4096) | k(4096) ], h*128+d
__device__ float g_re[1024 * 4096];          // rel_enc rows p in [544,1568), [p'][h*128+d]
__device__ float g_outer[1024 * 256];        // [i][ outer_q(128) | outer_k(128) ]
__device__ float g_tq_hip[33554432];         // [h][i][p']  (32 x 1024 x 1024)
__device__ float g_tk_hip[33554432];
__device__ float g_tq_iph[33554432];         // [i][p'][h]
__device__ float g_tk_iph[33554432];
__device__ float g_sim[33554432];            // [h][i][j]

// ---------------------------------------------------------------------------
__global__ void pool_gelu_kernel(const float* __restrict__ single)
{
    const int i = blockIdx.x;      // pooled token 0..1023
    const int c = threadIdx.x;     // channel 0..767
    const float* p = single + ((size_t)i * 16) * 768 + c;
    float s = 0.f;
#pragma unroll
    for (int t = 0; t < 16; t++) s += p[t * 768];
    s *= 0.0625f;
    g_pooled[i * 768 + c] = s;
    g_gelu[i * 768 + c] = 0.5f * s * (1.f + erff(s * 0.7071067811865475f));
}

// ---------------------------------------------------------------------------
// C[M,N] = A[M,K] * B[N,K]^T (+ optional per-k bias on A, per-col bias on C)
// 128x128 tile, 256 threads, 8x8 per-thread micro-tile, k-step 8.
// mode selects operand wiring (all dims here are multiples of the tile).
// ---------------------------------------------------------------------------
__global__ void __launch_bounds__(256) sgemm_nt(int mode,
    const float* __restrict__ X0, const float* __restrict__ X1,
    const float* __restrict__ X2)
{
    const float *A, *B;
    float *C;
    const float *Ab = nullptr, *Cb = nullptr;
    int lda, ldb, ldc, K;
    const int z = blockIdx.z;
    switch (mode) {
    case 0:  // qk = pooled @ w_qk^T        M=1024 N=8192 K=768
        A = g_pooled; lda = 768; B = X0; ldb = 768; C = g_qk; ldc = 8192; K = 768; break;
    case 1:  // rel_enc rows 544.. = rpf @ w_rel^T + b_rel   M=1024 N=4096 K=768
        A = X0 + 544 * 768; lda = 768; B = X1; ldb = 768; C = g_re; ldc = 4096;
        Cb = X2; K = 768; break;
    case 2:  // outer = gelu @ w_outer^T    M=1024 N=256 K=768
        A = g_gelu; lda = 768; B = X0; ldb = 768; C = g_outer; ldc = 256; K = 768; break;
    case 3:  // t_q[h] = (q_h + qbias_h) @ re_h^T   per-head batch z
        A = g_qk + z * 128; lda = 8192; Ab = X0 + z * 128;
        B = g_re + z * 128; ldb = 4096;
        C = g_tq_hip + (size_t)z * 1048576; ldc = 1024; K = 128; break;
    case 4:  // t_k[h]
        A = g_qk + 4096 + z * 128; lda = 8192; Ab = X0 + 4096 + z * 128;
        B = g_re + z * 128; ldb = 4096;
        C = g_tk_hip + (size_t)z * 1048576; ldc = 1024; K = 128; break;
    default: // sim[h] = q_h @ k_h^T
        A = g_qk + z * 128; lda = 8192;
        B = g_qk + 4096 + z * 128; ldb = 8192;
        C = g_sim + (size_t)z * 1048576; ldc = 1024; K = 128; break;
    }

    __shared__ float As[8][128];
    __shared__ float Bs[8][128];
    const int tid = threadIdx.x;
    const int bm = blockIdx.y << 7, bn = blockIdx.x << 7;
    const int lrow = tid >> 1;
    const int lk = (tid & 1) << 2;
    const int tr = (tid >> 4) << 3;
    const int tc = (tid & 15) << 3;

    float acc[8][8];
#pragma unroll
    for (int u = 0; u < 8; u++)
#pragma unroll
        for (int v = 0; v < 8; v++) acc[u][v] = 0.f;

    const float* Ap = A + (size_t)(bm + lrow) * lda + lk;
    const float* Bp = B + (size_t)(bn + lrow) * ldb + lk;

    for (int k0 = 0; k0 < K; k0 += 8) {
        float4 av = *(const float4*)(Ap + k0);
        float4 bv = *(const float4*)(Bp + k0);
        if (Ab) {
            float4 ab = *(const float4*)(Ab + k0 + lk);
            av.x += ab.x; av.y += ab.y; av.z += ab.z; av.w += ab.w;
        }
        As[lk + 0][lrow] = av.x; As[lk + 1][lrow] = av.y;
        As[lk + 2][lrow] = av.z; As[lk + 3][lrow] = av.w;
        Bs[lk + 0][lrow] = bv.x; Bs[lk + 1][lrow] = bv.y;
        Bs[lk + 2][lrow] = bv.z; Bs[lk + 3][lrow] = bv.w;
        __syncthreads();
#pragma unroll
        for (int kk = 0; kk < 8; kk++) {
            float4 a0 = *(const float4*)&As[kk][tr];
            float4 a1 = *(const float4*)&As[kk][tr + 4];
            float4 b0 = *(const float4*)&Bs[kk][tc];
            float4 b1 = *(const float4*)&Bs[kk][tc + 4];
            float ar[8] = {a0.x, a0.y, a0.z, a0.w, a1.x, a1.y, a1.z, a1.w};
            float br[8] = {b0.x, b0.y, b0.z, b0.w, b1.x, b1.y, b1.z, b1.w};
#pragma unroll
            for (int u = 0; u < 8; u++)
#pragma unroll
                for (int v = 0; v < 8; v++) acc[u][v] += ar[u] * br[v];
        }
        __syncthreads();
    }

#pragma unroll
    for (int u = 0; u < 8; u++) {
        float* crow = C + (size_t)(bm + tr + u) * ldc + bn + tc;
        float4 v0 = {acc[u][0], acc[u][1], acc[u][2], acc[u][3]};
        float4 v1 = {acc[u][4], acc[u][5], acc[u][6], acc[u][7]};
        if (Cb) {
            const float* cb = Cb + bn + tc;
            v0.x += cb[0]; v0.y += cb[1]; v0.z += cb[2]; v0.w += cb[3];
            v1.x += cb[4]; v1.y += cb[5]; v1.z += cb[6]; v1.w += cb[7];
        }
        *(float4*)crow = v0;
        *((float4*)crow + 1) = v1;
    }
}

// ---------------------------------------------------------------------------
// [h][i][p'] -> [i][p'][h] so the head-mixing gather reads ~contiguous bytes
// ---------------------------------------------------------------------------
__global__ void __launch_bounds__(256) transpose_t()
{
    const float* in = blockIdx.z ? g_tk_hip : g_tq_hip;
    float* o = blockIdx.z ? g_tk_iph : g_tq_iph;
    __shared__ float s[32][65];
    const int i = blockIdx.y;
    const int p0 = blockIdx.x << 6;
    const int tid = threadIdx.x;
    for (int idx = tid; idx < 2048; idx += 256) {
        int h = idx >> 6, p = idx & 63;
        s[h][p] = in[((size_t)h << 20) + ((size_t)i << 10) + p0 + p];
    }
    __syncthreads();
    for (int idx = tid; idx < 2048; idx += 256) {
        int p = idx >> 5, h = idx & 31;
        o[(((size_t)i << 10) + p0 + p) * 32 + h] = s[h][p];
    }
}

// ---------------------------------------------------------------------------
// Final fused kernel: one block per (i, 64-wide j tile).
//   s[h][j] = sim[h][i][j] + 0.5*(gather(t_q row i) + gather(t_k row j))
//   out[i][j][c] = sum_h s[h][j]*w_pair[c][h] + b_pair[c] + outer_q[i][c]
//                  + outer_k[j][c]
// Gather map (derived from relative_shift over the trailing (p,h) axes, then
// crop by 512):  m = 18432 + 32*j + h ; P = m/33 ; r = m%33 ;
//   value = (r==0) ? 0 : t[i][P][r-1]; with t stored [i][p'][h], p'=P-544,
//   the flat offset is exactly m - P - 17409.
// ---------------------------------------------------------------------------
__global__ void __launch_bounds__(256) final_kernel(
    const float* __restrict__ w_pair, const float* __restrict__ b_pair,
    float* __restrict__ out)
{
    const int i = blockIdx.y;
    const int j0 = blockIdx.x << 6;
    __shared__ float s_s[32][64];     // combined sim tile
    __shared__ float s_wp[32][132];   // w_pair transposed [h][c]
    __shared__ float s_tq[1988];      // contiguous t_q window for row i
    __shared__ float s_tk[64][33];    // 32-float window per j row of t_k
    __shared__ float s_bo[128];       // b_pair + outer_q[i]
    const int tid = threadIdx.x;

    for (int idx = tid; idx < 4096; idx += 256) {
        float v = w_pair[idx];              // [c][h]
        s_wp[idx & 31][idx >> 5] = v;
    }
    if (tid < 128) s_bo[tid] = b_pair[tid] + g_outer[i * 256 + tid];

    for (int idx = tid; idx < 2048; idx += 256) {
        int h = idx >> 6, jj = idx & 63;
        s_s[h][jj] = g_sim[((size_t)h << 20) + ((size_t)i << 10) + (j0 + jj)];
    }

    const int F0 = 18432 + (j0 << 5);
    const int f0 = F0 - F0 / 33 - 17409;
    {
        const float* tqb = g_tq_iph + ((size_t)i << 15) + f0;
        for (int idx = tid; idx < 1988; idx += 256) s_tq[idx] = tqb[idx];
    }
    const int M0 = 18432 + (i << 5);
    const int gb = M0 - M0 / 33 - 17409;
    for (int idx = tid; idx < 2048; idx += 256) {
        int jj = idx >> 5, x = idx & 31;
        s_tk[jj][x] = g_tk_iph[((size_t)(j0 + jj) << 15) + gb + x];
    }
    __syncthreads();

    for (int idx = tid; idx < 2048; idx += 256) {
        int h = idx >> 6, jj = idx & 63;
        int m = F0 + (jj << 5) + h;
        int P = m / 33, r = m - P * 33;
        float tq = (r == 0) ? 0.f : s_tq[m - P - 17409 - f0];
        int mi = M0 + h;
        int Pi = mi / 33, ri = mi - Pi * 33;
        float tk = (ri == 0) ? 0.f : s_tk[jj][mi - Pi - 17409 - gb];
        s_s[h][jj] += 0.5f * (tq + tk);
    }
    __syncthreads();

    // 64j x 128c = (64x32)*(32x128) smem GEMM, 4x8 per thread
    const int tr = (tid >> 4) << 2;
    const int tc = (tid & 15) << 3;
    float acc[4][8];
#pragma unroll
    for (int u = 0; u < 4; u++)
#pragma unroll
        for (int v = 0; v < 8; v++) acc[u][v] = 0.f;

#pragma unroll
    for (int h = 0; h < 32; h++) {
        float4 a0 = *(const float4*)&s_s[h][tr];
        float4 b0 = *(const float4*)&s_wp[h][tc];
        float4 b1 = *(const float4*)&s_wp[h][tc + 4];
        float ar[4] = {a0.x, a0.y, a0.z, a0.w};
        float br[8] = {b0.x, b0.y, b0.z, b0.w, b1.x, b1.y, b1.z, b1.w};
#pragma unroll
        for (int u = 0; u < 4; u++)
#pragma unroll
            for (int v = 0; v < 8; v++) acc[u][v] += ar[u] * br[v];
    }

#pragma unroll
    for (int u = 0; u < 4; u++) {
        const int j = j0 + tr + u;
        const float* okp = g_outer + j * 256 + 128 + tc;
        float4 k0 = *(const float4*)okp;
        float4 k1 = *(const float4*)(okp + 4);
        float4 o0, o1;
        o0.x = acc[u][0] + s_bo[tc + 0] + k0.x;
        o0.y = acc[u][1] + s_bo[tc + 1] + k0.y;
        o0.z = acc[u][2] + s_bo[tc + 2] + k0.z;
        o0.w = acc[u][3] + s_bo[tc + 3] + k0.w;
        o1.x = acc[u][4] + s_bo[tc + 4] + k1.x;
        o1.y = acc[u][5] + s_bo[tc + 5] + k1.y;
        o1.z = acc[u][6] + s_bo[tc + 6] + k1.z;
        o1.w = acc[u][7] + s_bo[tc + 7] + k1.w;
        float* op = out + ((((size_t)i << 10) + j) << 7) + tc;
        *(float4*)op = o0;
        *((float4*)op + 1) = o1;
    }
}

// ---------------------------------------------------------------------------
extern "C" void kernel_launch(void* const* d_in, const int* in_sizes, int n_in,
                              void* d_out, int out_size)
{
    (void)in_sizes; (void)n_in; (void)out_size;
    const float* single        = (const float*)d_in[0];
    const float* rel_pos_feats = (const float*)d_in[1];
    const float* w_qk          = (const float*)d_in[2];
    const float* w_outer       = (const float*)d_in[3];
    const float* w_pair        = (const float*)d_in[4];
    const float* b_pair        = (const float*)d_in[5];
    const float* w_rel         = (const float*)d_in[6];
    const float* b_rel         = (const float*)d_in[7];
    const float* qk_bias       = (const float*)d_in[8];
    float* out = (float*)d_out;

    pool_gelu_kernel<<<1024, 768>>>(single);
    sgemm_nt<<<dim3(64, 8, 1), 256>>>(0, w_qk, nullptr, nullptr);
    sgemm_nt<<<dim3(32, 8, 1), 256>>>(1, rel_pos_feats, w_rel, b_rel);
    sgemm_nt<<<dim3(2, 8, 1), 256>>>(2, w_outer, nullptr, nullptr);
    sgemm_nt<<<dim3(8, 8, 32), 256>>>(3, qk_bias, nullptr, nullptr);
    sgemm_nt<<<dim3(8, 8, 32), 256>>>(4, qk_bias, nullptr, nullptr);
    sgemm_nt<<<dim3(8, 8, 32), 256>>>(5, nullptr, nullptr, nullptr);
    transpose_t<<<dim3(16, 1024, 2), 256>>>();
    final_kernel<<<dim3(16, 1024, 1), 256>>>(w_pair, b_pair, out);
}

// round 6
// speedup vs baseline: 1.2703x; 1.2703x over previous
#include <cuda_runtime.h>
#include <cuda_bf16.h>
#include <mma.h>
#include <math.h>
#include <stdint.h>

using namespace nvcuda;

// ---------------------------------------------------------------------------
// SingleToPairwise — WMMA bf16-split GEMM pipeline, fp32 intermediates.
// Split precision: x = hi + lo (bf16); A@B ~= Ah@Bh + Ah@Bl + Al@Bh
// ---------------------------------------------------------------------------

__device__ float g_pooled[1024 * 768];
__device__ float g_gelu[1024 * 768];
__device__ float g_qk[1024 * 8192];    // [i][ q(4096) | k(4096) ]
__device__ float g_re[1024 * 4096];    // rel_enc rows 544..1567, [p'][h*128+d]
__device__ float g_outer[1024 * 256];
__device__ float g_vq[32 * 1024];
__device__ float g_vk[32 * 1024];
__device__ float g_tq_hip[33554432];   // [h][i][p']
__device__ float g_tk_hip[33554432];
__device__ float g_tq_iph[33554432];   // [i][p'][h]
__device__ float g_tk_iph[33554432];
__device__ float g_sim[33554432];      // [h][i][j]

// ---------------------------------------------------------------------------
__global__ void pool_gelu_kernel(const float* __restrict__ single)
{
    const int i = blockIdx.x;
    const int c = threadIdx.x;
    const float* p = single + ((size_t)i * 16) * 768 + c;
    float s = 0.f;
#pragma unroll
    for (int t = 0; t < 16; t++) s += p[t * 768];
    s *= 0.0625f;
    g_pooled[i * 768 + c] = s;
    g_gelu[i * 768 + c] = 0.5f * s * (1.f + erff(s * 0.7071067811865475f));
}

// vq[h][p] = sum_d qb[h][d]*re[p][h*128+d]; vk likewise
__global__ void __launch_bounds__(256) bias_vec(const float* __restrict__ qk_bias)
{
    int idx = blockIdx.x * 256 + threadIdx.x;   // 32768
    int h = idx >> 10, p = idx & 1023;
    const float* qb = qk_bias + h * 128;
    const float* kb = qk_bias + 4096 + h * 128;
    const float* re = g_re + p * 4096 + h * 128;
    float sq = 0.f, sk = 0.f;
#pragma unroll 8
    for (int d = 0; d < 128; d++) {
        float r = re[d];
        sq += qb[d] * r;
        sk += kb[d] * r;
    }
    g_vq[idx] = sq;
    g_vk[idx] = sk;
}

// ---------------------------------------------------------------------------
// WMMA bf16-split GEMM. C[M,N] = A[M,K](f32) @ B[N,K](f32)^T (+col bias)
// Block 128x128, 8 warps (64x32 each), K-chunk 32, fp32->split-bf16 on stage.
// ---------------------------------------------------------------------------
#define SMS 40          // smem row stride in bf16 elements (32 + 8 pad)
#define TILE_B 10240    // bytes per 128xSMS bf16 region

__device__ __forceinline__ void stage_split(
    __nv_bfloat16* __restrict__ sh, __nv_bfloat16* __restrict__ sl,
    const float* __restrict__ src, int ld, int row0, int kofs, int tid)
{
#pragma unroll
    for (int r = 0; r < 4; r++) {
        int gidx = tid + (r << 8);            // 0..1023
        int m = gidx >> 3, kg = gidx & 7;     // 128 rows x 8 groups of 4
        float4 v = *(const float4*)(src + (size_t)(row0 + m) * ld + kofs + (kg << 2));
        __nv_bfloat16 h0 = __float2bfloat16(v.x);
        __nv_bfloat16 h1 = __float2bfloat16(v.y);
        __nv_bfloat16 h2 = __float2bfloat16(v.z);
        __nv_bfloat16 h3 = __float2bfloat16(v.w);
        __nv_bfloat16 l0 = __float2bfloat16(v.x - __bfloat162float(h0));
        __nv_bfloat16 l1 = __float2bfloat16(v.y - __bfloat162float(h1));
        __nv_bfloat16 l2 = __float2bfloat16(v.z - __bfloat162float(h2));
        __nv_bfloat16 l3 = __float2bfloat16(v.w - __bfloat162float(h3));
        int o = m * SMS + (kg << 2);
        *(__nv_bfloat162*)&sh[o]     = __halves2bfloat162(h0, h1);
        *(__nv_bfloat162*)&sh[o + 2] = __halves2bfloat162(h2, h3);
        *(__nv_bfloat162*)&sl[o]     = __halves2bfloat162(l0, l1);
        *(__nv_bfloat162*)&sl[o + 2] = __halves2bfloat162(l2, l3);
    }
}

__global__ void __launch_bounds__(256) wmma_gemm(int mode,
    const float* __restrict__ X0, const float* __restrict__ X1,
    const float* __restrict__ X2)
{
    __shared__ __align__(16) char smbuf[4 * TILE_B];
    __nv_bfloat16* sAh = (__nv_bfloat16*)smbuf;
    __nv_bfloat16* sAl = (__nv_bfloat16*)(smbuf + TILE_B);
    __nv_bfloat16* sBh = (__nv_bfloat16*)(smbuf + 2 * TILE_B);
    __nv_bfloat16* sBl = (__nv_bfloat16*)(smbuf + 3 * TILE_B);

    const int tid = threadIdx.x;
    const int wid = tid >> 5, lane = tid & 31;
    const int wm = (wid & 1) * 64, wn = (wid >> 1) * 32;
    const int z = blockIdx.z;
    const int bm = blockIdx.y << 7, bn = blockIdx.x << 7;

    const float *A, *B;
    float* C;
    const float* cb = nullptr;
    int lda, ldb, ldc, K;
    switch (mode) {
    case 0:   // qk = pooled @ w_qk^T
        A = g_pooled; lda = 768; B = X0; ldb = 768;
        C = g_qk; ldc = 8192; K = 768; break;
    case 1:   // re = rpf[544..] @ w_rel^T + b_rel
        A = X0 + 544 * 768; lda = 768; B = X1; ldb = 768;
        C = g_re; ldc = 4096; K = 768; cb = X2; break;
    case 3:   // t_q[h] = q_h @ re_h^T + vq[h]
        A = g_qk + z * 128; lda = 8192; B = g_re + z * 128; ldb = 4096;
        C = g_tq_hip + ((size_t)z << 20); ldc = 1024; K = 128; cb = g_vq + z * 1024; break;
    case 4:   // t_k[h]
        A = g_qk + 4096 + z * 128; lda = 8192; B = g_re + z * 128; ldb = 4096;
        C = g_tk_hip + ((size_t)z << 20); ldc = 1024; K = 128; cb = g_vk + z * 1024; break;
    default:  // sim[h] = q_h @ k_h^T
        A = g_qk + z * 128; lda = 8192; B = g_qk + 4096 + z * 128; ldb = 8192;
        C = g_sim + ((size_t)z << 20); ldc = 1024; K = 128; break;
    }

    wmma::fragment<wmma::accumulator, 16, 16, 16, float> acc[4][2];
#pragma unroll
    for (int mf = 0; mf < 4; mf++)
#pragma unroll
        for (int nf = 0; nf < 2; nf++) wmma::fill_fragment(acc[mf][nf], 0.f);

    const int nK = K >> 5;
    for (int kc = 0; kc < nK; kc++) {
        const int kofs = kc << 5;
        __syncthreads();
        stage_split(sAh, sAl, A, lda, bm, kofs, tid);
        stage_split(sBh, sBl, B, ldb, bn, kofs, tid);
        __syncthreads();

#pragma unroll
        for (int ks = 0; ks < 2; ks++) {
            const int kb = ks << 4;
            wmma::fragment<wmma::matrix_a, 16, 16, 16, __nv_bfloat16, wmma::row_major> ah[4], al[4];
            wmma::fragment<wmma::matrix_b, 16, 16, 16, __nv_bfloat16, wmma::col_major> bh[2], bl[2];
#pragma unroll
            for (int mf = 0; mf < 4; mf++) {
                wmma::load_matrix_sync(ah[mf], sAh + (wm + mf * 16) * SMS + kb, SMS);
                wmma::load_matrix_sync(al[mf], sAl + (wm + mf * 16) * SMS + kb, SMS);
            }
#pragma unroll
            for (int nf = 0; nf < 2; nf++) {
                wmma::load_matrix_sync(bh[nf], sBh + (wn + nf * 16) * SMS + kb, SMS);
                wmma::load_matrix_sync(bl[nf], sBl + (wn + nf * 16) * SMS + kb, SMS);
            }
#pragma unroll
            for (int mf = 0; mf < 4; mf++)
#pragma unroll
                for (int nf = 0; nf < 2; nf++) {
                    wmma::mma_sync(acc[mf][nf], ah[mf], bh[nf], acc[mf][nf]);
                    wmma::mma_sync(acc[mf][nf], ah[mf], bl[nf], acc[mf][nf]);
                    wmma::mma_sync(acc[mf][nf], al[mf], bh[nf], acc[mf][nf]);
                }
        }
    }

    // epilogue via per-warp smem scratch (aliases smbuf after sync)
    __syncthreads();
    float* sc = (float*)smbuf + wid * 256;
    const int rr = lane >> 1;
    const int cc = (lane & 1) << 3;
#pragma unroll
    for (int mf = 0; mf < 4; mf++)
#pragma unroll
        for (int nf = 0; nf < 2; nf++) {
            wmma::store_matrix_sync(sc, acc[mf][nf], 16, wmma::mem_row_major);
            __syncwarp();
            const int row = bm + wm + mf * 16 + rr;
            const int col = bn + wn + nf * 16 + cc;
            float4 v0 = *(float4*)&sc[rr * 16 + cc];
            float4 v1 = *(float4*)&sc[rr * 16 + cc + 4];
            if (cb) {
                const float* b = cb + col;
                v0.x += b[0]; v0.y += b[1]; v0.z += b[2]; v0.w += b[3];
                v1.x += b[4]; v1.y += b[5]; v1.z += b[6]; v1.w += b[7];
            }
            float* op = C + (size_t)row * ldc + col;
            *(float4*)op = v0;
            *((float4*)op + 1) = v1;
            __syncwarp();
        }
}

// ---------------------------------------------------------------------------
// fp32 SGEMM for outer (tiny: 1024x256x768)  [proven in R2]
// ---------------------------------------------------------------------------
__global__ void __launch_bounds__(256) sgemm_outer(const float* __restrict__ w_outer)
{
    const float* A = g_gelu;
    const float* B = w_outer;
    float* C = g_outer;
    const int lda = 768, ldb = 768, ldc = 256, K = 768;

    __shared__ float As[8][128];
    __shared__ float Bs[8][128];
    const int tid = threadIdx.x;
    const int bm = blockIdx.y << 7, bn = blockIdx.x << 7;
    const int lrow = tid >> 1;
    const int lk = (tid & 1) << 2;
    const int tr = (tid >> 4) << 3;
    const int tc = (tid & 15) << 3;

    float acc[8][8];
#pragma unroll
    for (int u = 0; u < 8; u++)
#pragma unroll
        for (int v = 0; v < 8; v++) acc[u][v] = 0.f;

    const float* Ap = A + (size_t)(bm + lrow) * lda + lk;
    const float* Bp = B + (size_t)(bn + lrow) * ldb + lk;

    for (int k0 = 0; k0 < K; k0 += 8) {
        float4 av = *(const float4*)(Ap + k0);
        float4 bv = *(const float4*)(Bp + k0);
        As[lk + 0][lrow] = av.x; As[lk + 1][lrow] = av.y;
        As[lk + 2][lrow] = av.z; As[lk + 3][lrow] = av.w;
        Bs[lk + 0][lrow] = bv.x; Bs[lk + 1][lrow] = bv.y;
        Bs[lk + 2][lrow] = bv.z; Bs[lk + 3][lrow] = bv.w;
        __syncthreads();
#pragma unroll
        for (int kk = 0; kk < 8; kk++) {
            float4 a0 = *(const float4*)&As[kk][tr];
            float4 a1 = *(const float4*)&As[kk][tr + 4];
            float4 b0 = *(const float4*)&Bs[kk][tc];
            float4 b1 = *(const float4*)&Bs[kk][tc + 4];
            float ar[8] = {a0.x, a0.y, a0.z, a0.w, a1.x, a1.y, a1.z, a1.w};
            float br[8] = {b0.x, b0.y, b0.z, b0.w, b1.x, b1.y, b1.z, b1.w};
#pragma unroll
            for (int u = 0; u < 8; u++)
#pragma unroll
                for (int v = 0; v < 8; v++) acc[u][v] += ar[u] * br[v];
        }
        __syncthreads();
    }
#pragma unroll
    for (int u = 0; u < 8; u++) {
        float* crow = C + (size_t)(bm + tr + u) * ldc + bn + tc;
        *(float4*)crow = make_float4(acc[u][0], acc[u][1], acc[u][2], acc[u][3]);
        *((float4*)crow + 1) = make_float4(acc[u][4], acc[u][5], acc[u][6], acc[u][7]);
    }
}

// ---------------------------------------------------------------------------
// [h][i][p'] -> [i][p'][h]   [proven in R2]
// ---------------------------------------------------------------------------
__global__ void __launch_bounds__(256) transpose_t()
{
    const float* in = blockIdx.z ? g_tk_hip : g_tq_hip;
    float* o = blockIdx.z ? g_tk_iph : g_tq_iph;
    __shared__ float s[32][65];
    const int i = blockIdx.y;
    const int p0 = blockIdx.x << 6;
    const int tid = threadIdx.x;
    for (int idx = tid; idx < 2048; idx += 256) {
        int h = idx >> 6, p = idx & 63;
        s[h][p] = in[((size_t)h << 20) + ((size_t)i << 10) + p0 + p];
    }
    __syncthreads();
    for (int idx = tid; idx < 2048; idx += 256) {
        int p = idx >> 5, h = idx & 31;
        o[(((size_t)i << 10) + p0 + p) * 32 + h] = s[h][p];
    }
}

// ---------------------------------------------------------------------------
// Final fused kernel (gather + 32->128 pair projection + outer sum) [proven R2]
// ---------------------------------------------------------------------------
__global__ void __launch_bounds__(256) final_kernel(
    const float* __restrict__ w_pair, const float* __restrict__ b_pair,
    float* __restrict__ out)
{
    const int i = blockIdx.y;
    const int j0 = blockIdx.x << 6;
    __shared__ float s_s[32][64];
    __shared__ float s_wp[32][132];
    __shared__ float s_tq[1988];
    __shared__ float s_tk[64][33];
    __shared__ float s_bo[128];
    const int tid = threadIdx.x;

    for (int idx = tid; idx < 4096; idx += 256) {
        float v = w_pair[idx];
        s_wp[idx & 31][idx >> 5] = v;
    }
    if (tid < 128) s_bo[tid] = b_pair[tid] + g_outer[i * 256 + tid];

    for (int idx = tid; idx < 2048; idx += 256) {
        int h = idx >> 6, jj = idx & 63;
        s_s[h][jj] = g_sim[((size_t)h << 20) + ((size_t)i << 10) + (j0 + jj)];
    }

    const int F0 = 18432 + (j0 << 5);
    const int f0 = F0 - F0 / 33 - 17409;
    {
        const float* tqb = g_tq_iph + ((size_t)i << 15) + f0;
        for (int idx = tid; idx < 1988; idx += 256) s_tq[idx] = tqb[idx];
    }
    const int M0 = 18432 + (i << 5);
    const int gb = M0 - M0 / 33 - 17409;
    for (int idx = tid; idx < 2048; idx += 256) {
        int jj = idx >> 5, x = idx & 31;
        s_tk[jj][x] = g_tk_iph[((size_t)(j0 + jj) << 15) + gb + x];
    }
    __syncthreads();

    for (int idx = tid; idx < 2048; idx += 256) {
        int h = idx >> 6, jj = idx & 63;
        int m = F0 + (jj << 5) + h;
        int P = m / 33, r = m - P * 33;
        float tq = (r == 0) ? 0.f : s_tq[m - P - 17409 - f0];
        int mi = M0 + h;
        int Pi = mi / 33, ri = mi - Pi * 33;
        float tk = (ri == 0) ? 0.f : s_tk[jj][mi - Pi - 17409 - gb];
        s_s[h][jj] += 0.5f * (tq + tk);
    }
    __syncthreads();

    const int tr = (tid >> 4) << 2;
    const int tc = (tid & 15) << 3;
    float acc[4][8];
#pragma unroll
    for (int u = 0; u < 4; u++)
#pragma unroll
        for (int v = 0; v < 8; v++) acc[u][v] = 0.f;

#pragma unroll
    for (int h = 0; h < 32; h++) {
        float4 a0 = *(const float4*)&s_s[h][tr];
        float4 b0 = *(const float4*)&s_wp[h][tc];
        float4 b1 = *(const float4*)&s_wp[h][tc + 4];
        float ar[4] = {a0.x, a0.y, a0.z, a0.w};
        float br[8] = {b0.x, b0.y, b0.z, b0.w, b1.x, b1.y, b1.z, b1.w};
#pragma unroll
        for (int u = 0; u < 4; u++)
#pragma unroll
            for (int v = 0; v < 8; v++) acc[u][v] += ar[u] * br[v];
    }

#pragma unroll
    for (int u = 0; u < 4; u++) {
        const int j = j0 + tr + u;
        const float* okp = g_outer + j * 256 + 128 + tc;
        float4 k0 = *(const float4*)okp;
        float4 k1 = *(const float4*)(okp + 4);
        float4 o0, o1;
        o0.x = acc[u][0] + s_bo[tc + 0] + k0.x;
        o0.y = acc[u][1] + s_bo[tc + 1] + k0.y;
        o0.z = acc[u][2] + s_bo[tc + 2] + k0.z;
        o0.w = acc[u][3] + s_bo[tc + 3] + k0.w;
        o1.x = acc[u][4] + s_bo[tc + 4] + k1.x;
        o1.y = acc[u][5] + s_bo[tc + 5] + k1.y;
        o1.z = acc[u][6] + s_bo[tc + 6] + k1.z;
        o1.w = acc[u][7] + s_bo[tc + 7] + k1.w;
        float* op = out + ((((size_t)i << 10) + j) << 7) + tc;
        *(float4*)op = o0;
        *((float4*)op + 1) = o1;
    }
}

// ---------------------------------------------------------------------------
extern "C" void kernel_launch(void* const* d_in, const int* in_sizes, int n_in,
                              void* d_out, int out_size)
{
    (void)in_sizes; (void)n_in; (void)out_size;
    const float* single        = (const float*)d_in[0];
    const float* rel_pos_feats = (const float*)d_in[1];
    const float* w_qk          = (const float*)d_in[2];
    const float* w_outer       = (const float*)d_in[3];
    const float* w_pair        = (const float*)d_in[4];
    const float* b_pair        = (const float*)d_in[5];
    const float* w_rel         = (const float*)d_in[6];
    const float* b_rel         = (const float*)d_in[7];
    const float* qk_bias       = (const float*)d_in[8];
    float* out = (float*)d_out;

    pool_gelu_kernel<<<1024, 768>>>(single);
    wmma_gemm<<<dim3(64, 8, 1), 256>>>(0, w_qk, nullptr, nullptr);       // qk
    wmma_gemm<<<dim3(32, 8, 1), 256>>>(1, rel_pos_feats, w_rel, b_rel);  // rel_enc
    sgemm_outer<<<dim3(2, 8, 1), 256>>>(w_outer);
    bias_vec<<<128, 256>>>(qk_bias);
    wmma_gemm<<<dim3(8, 8, 32), 256>>>(3, nullptr, nullptr, nullptr);    // t_q
    wmma_gemm<<<dim3(8, 8, 32), 256>>>(4, nullptr, nullptr, nullptr);    // t_k
    wmma_gemm<<<dim3(8, 8, 32), 256>>>(5, nullptr, nullptr, nullptr);    // sim
    transpose_t<<<dim3(16, 1024, 2), 256>>>();
    final_kernel<<<dim3(16, 1024, 1), 256>>>(w_pair, b_pair, out);
}

// round 7
// speedup vs baseline: 1.3037x; 1.0263x over previous
#include <cuda_runtime.h>
#include <cuda_bf16.h>
#include <mma.h>
#include <math.h>
#include <stdint.h>

using namespace nvcuda;

// ---------------------------------------------------------------------------
// SingleToPairwise — WMMA bf16-split GEMM pipeline, fp32 intermediates.
// Split precision: x = hi + lo (bf16); A@B ~= Ah@Bh + Ah@Bl + Al@Bh
// R7: register-prefetch pipelined GEMM + split-K outer.
// ---------------------------------------------------------------------------

__device__ float g_pooled[1024 * 768];
__device__ float g_gelu[1024 * 768];
__device__ float g_qk[1024 * 8192];    // [i][ q(4096) | k(4096) ]
__device__ float g_re[1024 * 4096];    // rel_enc rows 544..1567, [p'][h*128+d]
__device__ float g_outer[1024 * 256];
__device__ float g_outer_part[6 * 1024 * 256];
__device__ float g_vq[32 * 1024];
__device__ float g_vk[32 * 1024];
__device__ float g_tq_hip[33554432];   // [h][i][p']
__device__ float g_tk_hip[33554432];
__device__ float g_tq_iph[33554432];   // [i][p'][h]
__device__ float g_tk_iph[33554432];
__device__ float g_sim[33554432];      // [h][i][j]

// ---------------------------------------------------------------------------
__global__ void pool_gelu_kernel(const float* __restrict__ single)
{
    const int i = blockIdx.x;
    const int c = threadIdx.x;
    const float* p = single + ((size_t)i * 16) * 768 + c;
    float s = 0.f;
#pragma unroll
    for (int t = 0; t < 16; t++) s += p[t * 768];
    s *= 0.0625f;
    g_pooled[i * 768 + c] = s;
    g_gelu[i * 768 + c] = 0.5f * s * (1.f + erff(s * 0.7071067811865475f));
}

// vq[h][p] = sum_d qb[h][d]*re[p][h*128+d]; vk likewise
__global__ void __launch_bounds__(256) bias_vec(const float* __restrict__ qk_bias)
{
    int idx = blockIdx.x * 256 + threadIdx.x;   // 32768
    int h = idx >> 10, p = idx & 1023;
    const float* qb = qk_bias + h * 128;
    const float* kb = qk_bias + 4096 + h * 128;
    const float* re = g_re + p * 4096 + h * 128;
    float sq = 0.f, sk = 0.f;
#pragma unroll 8
    for (int d = 0; d < 128; d++) {
        float r = re[d];
        sq += qb[d] * r;
        sk += kb[d] * r;
    }
    g_vq[idx] = sq;
    g_vk[idx] = sk;
}

// ---------------------------------------------------------------------------
// WMMA bf16-split GEMM. C[M,N] = A[M,K](f32) @ B[N,K](f32)^T (+col bias)
// Block 128x128, 8 warps (64x32 each), K-chunk 32, register-prefetch pipeline.
// ---------------------------------------------------------------------------
#define SMS 40          // smem row stride in bf16 elements (32 + 8 pad)
#define TILE_B 10240    // bytes per 128xSMS bf16 region

__device__ __forceinline__ void ld4(float4* v, const float* __restrict__ src,
                                    int ld, int row0, int kofs, int tid)
{
#pragma unroll
    for (int r = 0; r < 4; r++) {
        int gidx = tid + (r << 8);            // 0..1023
        int m = gidx >> 3, kg = gidx & 7;     // 128 rows x 8 groups of 4
        v[r] = *(const float4*)(src + (size_t)(row0 + m) * ld + kofs + (kg << 2));
    }
}

__device__ __forceinline__ void st4(__nv_bfloat16* __restrict__ sh,
                                    __nv_bfloat16* __restrict__ sl,
                                    const float4* v, int tid)
{
#pragma unroll
    for (int r = 0; r < 4; r++) {
        int gidx = tid + (r << 8);
        int m = gidx >> 3, kg = gidx & 7;
        float4 w = v[r];
        __nv_bfloat16 h0 = __float2bfloat16(w.x);
        __nv_bfloat16 h1 = __float2bfloat16(w.y);
        __nv_bfloat16 h2 = __float2bfloat16(w.z);
        __nv_bfloat16 h3 = __float2bfloat16(w.w);
        __nv_bfloat16 l0 = __float2bfloat16(w.x - __bfloat162float(h0));
        __nv_bfloat16 l1 = __float2bfloat16(w.y - __bfloat162float(h1));
        __nv_bfloat16 l2 = __float2bfloat16(w.z - __bfloat162float(h2));
        __nv_bfloat16 l3 = __float2bfloat16(w.w - __bfloat162float(h3));
        int o = m * SMS + (kg << 2);
        *(__nv_bfloat162*)&sh[o]     = __halves2bfloat162(h0, h1);
        *(__nv_bfloat162*)&sh[o + 2] = __halves2bfloat162(h2, h3);
        *(__nv_bfloat162*)&sl[o]     = __halves2bfloat162(l0, l1);
        *(__nv_bfloat162*)&sl[o + 2] = __halves2bfloat162(l2, l3);
    }
}

__global__ void __launch_bounds__(256) wmma_gemm(int mode,
    const float* __restrict__ X0, const float* __restrict__ X1,
    const float* __restrict__ X2)
{
    __shared__ __align__(16) char smbuf[4 * TILE_B];
    __nv_bfloat16* sAh = (__nv_bfloat16*)smbuf;
    __nv_bfloat16* sAl = (__nv_bfloat16*)(smbuf + TILE_B);
    __nv_bfloat16* sBh = (__nv_bfloat16*)(smbuf + 2 * TILE_B);
    __nv_bfloat16* sBl = (__nv_bfloat16*)(smbuf + 3 * TILE_B);

    const int tid = threadIdx.x;
    const int wid = tid >> 5, lane = tid & 31;
    const int wm = (wid & 1) * 64, wn = (wid >> 1) * 32;
    const int z = blockIdx.z;
    const int bm = blockIdx.y << 7, bn = blockIdx.x << 7;

    const float *A, *B;
    float* C;
    const float* cb = nullptr;
    int lda, ldb, ldc, K;
    switch (mode) {
    case 0:   // qk = pooled @ w_qk^T
        A = g_pooled; lda = 768; B = X0; ldb = 768;
        C = g_qk; ldc = 8192; K = 768; break;
    case 1:   // re = rpf[544..] @ w_rel^T + b_rel
        A = X0 + 544 * 768; lda = 768; B = X1; ldb = 768;
        C = g_re; ldc = 4096; K = 768; cb = X2; break;
    case 3:   // t_q[h] = q_h @ re_h^T + vq[h]
        A = g_qk + z * 128; lda = 8192; B = g_re + z * 128; ldb = 4096;
        C = g_tq_hip + ((size_t)z << 20); ldc = 1024; K = 128; cb = g_vq + z * 1024; break;
    case 4:   // t_k[h]
        A = g_qk + 4096 + z * 128; lda = 8192; B = g_re + z * 128; ldb = 4096;
        C = g_tk_hip + ((size_t)z << 20); ldc = 1024; K = 128; cb = g_vk + z * 1024; break;
    default:  // sim[h] = q_h @ k_h^T
        A = g_qk + z * 128; lda = 8192; B = g_qk + 4096 + z * 128; ldb = 8192;
        C = g_sim + ((size_t)z << 20); ldc = 1024; K = 128; break;
    }

    wmma::fragment<wmma::accumulator, 16, 16, 16, float> acc[4][2];
#pragma unroll
    for (int mf = 0; mf < 4; mf++)
#pragma unroll
        for (int nf = 0; nf < 2; nf++) wmma::fill_fragment(acc[mf][nf], 0.f);

    const int nK = K >> 5;

    // prologue: stage chunk 0
    {
        float4 pa[4], pb[4];
        ld4(pa, A, lda, bm, 0, tid);
        ld4(pb, B, ldb, bn, 0, tid);
        st4(sAh, sAl, pa, tid);
        st4(sBh, sBl, pb, tid);
    }
    __syncthreads();

    for (int kc = 0; kc < nK; kc++) {
        // prefetch next chunk into registers (overlaps with compute below)
        float4 pa[4], pb[4];
        const bool more = (kc + 1 < nK);
        if (more) {
            const int kofs = (kc + 1) << 5;
            ld4(pa, A, lda, bm, kofs, tid);
            ld4(pb, B, ldb, bn, kofs, tid);
        }

#pragma unroll
        for (int ks = 0; ks < 2; ks++) {
            const int kb = ks << 4;
            wmma::fragment<wmma::matrix_a, 16, 16, 16, __nv_bfloat16, wmma::row_major> ah[4], al[4];
            wmma::fragment<wmma::matrix_b, 16, 16, 16, __nv_bfloat16, wmma::col_major> bh[2], bl[2];
#pragma unroll
            for (int mf = 0; mf < 4; mf++) {
                wmma::load_matrix_sync(ah[mf], sAh + (wm + mf * 16) * SMS + kb, SMS);
                wmma::load_matrix_sync(al[mf], sAl + (wm + mf * 16) * SMS + kb, SMS);
            }
#pragma unroll
            for (int nf = 0; nf < 2; nf++) {
                wmma::load_matrix_sync(bh[nf], sBh + (wn + nf * 16) * SMS + kb, SMS);
                wmma::load_matrix_sync(bl[nf], sBl + (wn + nf * 16) * SMS + kb, SMS);
            }
#pragma unroll
            for (int mf = 0; mf < 4; mf++)
#pragma unroll
                for (int nf = 0; nf < 2; nf++) {
                    wmma::mma_sync(acc[mf][nf], ah[mf], bh[nf], acc[mf][nf]);
                    wmma::mma_sync(acc[mf][nf], ah[mf], bl[nf], acc[mf][nf]);
                    wmma::mma_sync(acc[mf][nf], al[mf], bh[nf], acc[mf][nf]);
                }
        }

        if (more) {
            __syncthreads();   // all warps done reading current chunk
            st4(sAh, sAl, pa, tid);
            st4(sBh, sBl, pb, tid);
            __syncthreads();   // staged chunk visible
        }
    }

    // epilogue via per-warp smem scratch (aliases smbuf after sync)
    __syncthreads();
    float* sc = (float*)smbuf + wid * 256;
    const int rr = lane >> 1;
    const int cc = (lane & 1) << 3;
#pragma unroll
    for (int mf = 0; mf < 4; mf++)
#pragma unroll
        for (int nf = 0; nf < 2; nf++) {
            wmma::store_matrix_sync(sc, acc[mf][nf], 16, wmma::mem_row_major);
            __syncwarp();
            const int row = bm + wm + mf * 16 + rr;
            const int col = bn + wn + nf * 16 + cc;
            float4 v0 = *(float4*)&sc[rr * 16 + cc];
            float4 v1 = *(float4*)&sc[rr * 16 + cc + 4];
            if (cb) {
                const float* b = cb + col;
                v0.x += b[0]; v0.y += b[1]; v0.z += b[2]; v0.w += b[3];
                v1.x += b[4]; v1.y += b[5]; v1.z += b[6]; v1.w += b[7];
            }
            float* op = C + (size_t)row * ldc + col;
            *(float4*)op = v0;
            *((float4*)op + 1) = v1;
            __syncwarp();
        }
}

// ---------------------------------------------------------------------------
// fp32 SGEMM for outer, split-K (6 x 128) -> partials, then reduce.
// ---------------------------------------------------------------------------
__global__ void __launch_bounds__(256) sgemm_outer_splitk(const float* __restrict__ w_outer)
{
    const int kz = blockIdx.z;                 // 0..5
    const float* A = g_gelu + kz * 128;
    const float* B = w_outer + kz * 128;
    float* C = g_outer_part + kz * 262144;
    const int lda = 768, ldb = 768, ldc = 256, K = 128;

    __shared__ float As[8][128];
    __shared__ float Bs[8][128];
    const int tid = threadIdx.x;
    const int bm = blockIdx.y << 7, bn = blockIdx.x << 7;
    const int lrow = tid >> 1;
    const int lk = (tid & 1) << 2;
    const int tr = (tid >> 4) << 3;
    const int tc = (tid & 15) << 3;

    float acc[8][8];
#pragma unroll
    for (int u = 0; u < 8; u++)
#pragma unroll
        for (int v = 0; v < 8; v++) acc[u][v] = 0.f;

    const float* Ap = A + (size_t)(bm + lrow) * lda + lk;
    const float* Bp = B + (size_t)(bn + lrow) * ldb + lk;

    for (int k0 = 0; k0 < K; k0 += 8) {
        float4 av = *(const float4*)(Ap + k0);
        float4 bv = *(const float4*)(Bp + k0);
        As[lk + 0][lrow] = av.x; As[lk + 1][lrow] = av.y;
        As[lk + 2][lrow] = av.z; As[lk + 3][lrow] = av.w;
        Bs[lk + 0][lrow] = bv.x; Bs[lk + 1][lrow] = bv.y;
        Bs[lk + 2][lrow] = bv.z; Bs[lk + 3][lrow] = bv.w;
        __syncthreads();
#pragma unroll
        for (int kk = 0; kk < 8; kk++) {
            float4 a0 = *(const float4*)&As[kk][tr];
            float4 a1 = *(const float4*)&As[kk][tr + 4];
            float4 b0 = *(const float4*)&Bs[kk][tc];
            float4 b1 = *(const float4*)&Bs[kk][tc + 4];
            float ar[8] = {a0.x, a0.y, a0.z, a0.w, a1.x, a1.y, a1.z, a1.w};
            float br[8] = {b0.x, b0.y, b0.z, b0.w, b1.x, b1.y, b1.z, b1.w};
#pragma unroll
            for (int u = 0; u < 8; u++)
#pragma unroll
                for (int v = 0; v < 8; v++) acc[u][v] += ar[u] * br[v];
        }
        __syncthreads();
    }
#pragma unroll
    for (int u = 0; u < 8; u++) {
        float* crow = C + (size_t)(bm + tr + u) * ldc + bn + tc;
        *(float4*)crow = make_float4(acc[u][0], acc[u][1], acc[u][2], acc[u][3]);
        *((float4*)crow + 1) = make_float4(acc[u][4], acc[u][5], acc[u][6], acc[u][7]);
    }
}

__global__ void __launch_bounds__(256) reduce_outer()
{
    int idx = blockIdx.x * 256 + threadIdx.x;   // 262144
    float s = 0.f;
#pragma unroll
    for (int z = 0; z < 6; z++) s += g_outer_part[z * 262144 + idx];
    g_outer[idx] = s;
}

// ---------------------------------------------------------------------------
// [h][i][p'] -> [i][p'][h]
// ---------------------------------------------------------------------------
__global__ void __launch_bounds__(256) transpose_t()
{
    const float* in = blockIdx.z ? g_tk_hip : g_tq_hip;
    float* o = blockIdx.z ? g_tk_iph : g_tq_iph;
    __shared__ float s[32][65];
    const int i = blockIdx.y;
    const int p0 = blockIdx.x << 6;
    const int tid = threadIdx.x;
    for (int idx = tid; idx < 2048; idx += 256) {
        int h = idx >> 6, p = idx & 63;
        s[h][p] = in[((size_t)h << 20) + ((size_t)i << 10) + p0 + p];
    }
    __syncthreads();
    for (int idx = tid; idx < 2048; idx += 256) {
        int p = idx >> 5, h = idx & 31;
        o[(((size_t)i << 10) + p0 + p) * 32 + h] = s[h][p];
    }
}

// ---------------------------------------------------------------------------
// Final fused kernel (gather + 32->128 pair projection + outer sum)
// ---------------------------------------------------------------------------
__global__ void __launch_bounds__(256) final_kernel(
    const float* __restrict__ w_pair, const float* __restrict__ b_pair,
    float* __restrict__ out)
{
    const int i = blockIdx.y;
    const int j0 = blockIdx.x << 6;
    __shared__ float s_s[32][64];
    __shared__ float s_wp[32][132];
    __shared__ float s_tq[1988];
    __shared__ float s_tk[64][33];
    __shared__ float s_bo[128];
    const int tid = threadIdx.x;

    for (int idx = tid; idx < 4096; idx += 256) {
        float v = w_pair[idx];
        s_wp[idx & 31][idx >> 5] = v;
    }
    if (tid < 128) s_bo[tid] = b_pair[tid] + g_outer[i * 256 + tid];

    for (int idx = tid; idx < 2048; idx += 256) {
        int h = idx >> 6, jj = idx & 63;
        s_s[h][jj] = g_sim[((size_t)h << 20) + ((size_t)i << 10) + (j0 + jj)];
    }

    const int F0 = 18432 + (j0 << 5);
    const int f0 = F0 - F0 / 33 - 17409;
    {
        const float* tqb = g_tq_iph + ((size_t)i << 15) + f0;
        for (int idx = tid; idx < 1988; idx += 256) s_tq[idx] = tqb[idx];
    }
    const int M0 = 18432 + (i << 5);
    const int gb = M0 - M0 / 33 - 17409;
    for (int idx = tid; idx < 2048; idx += 256) {
        int jj = idx >> 5, x = idx & 31;
        s_tk[jj][x] = g_tk_iph[((size_t)(j0 + jj) << 15) + gb + x];
    }
    __syncthreads();

    for (int idx = tid; idx < 2048; idx += 256) {
        int h = idx >> 6, jj = idx & 63;
        int m = F0 + (jj << 5) + h;
        int P = m / 33, r = m - P * 33;
        float tq = (r == 0) ? 0.f : s_tq[m - P - 17409 - f0];
        int mi = M0 + h;
        int Pi = mi / 33, ri = mi - Pi * 33;
        float tk = (ri == 0) ? 0.f : s_tk[jj][mi - Pi - 17409 - gb];
        s_s[h][jj] += 0.5f * (tq + tk);
    }
    __syncthreads();

    const int tr = (tid >> 4) << 2;
    const int tc = (tid & 15) << 3;
    float acc[4][8];
#pragma unroll
    for (int u = 0; u < 4; u++)
#pragma unroll
        for (int v = 0; v < 8; v++) acc[u][v] = 0.f;

#pragma unroll
    for (int h = 0; h < 32; h++) {
        float4 a0 = *(const float4*)&s_s[h][tr];
        float4 b0 = *(const float4*)&s_wp[h][tc];
        float4 b1 = *(const float4*)&s_wp[h][tc + 4];
        float ar[4] = {a0.x, a0.y, a0.z, a0.w};
        float br[8] = {b0.x, b0.y, b0.z, b0.w, b1.x, b1.y, b1.z, b1.w};
#pragma unroll
        for (int u = 0; u < 4; u++)
#pragma unroll
            for (int v = 0; v < 8; v++) acc[u][v] += ar[u] * br[v];
    }

#pragma unroll
    for (int u = 0; u < 4; u++) {
        const int j = j0 + tr + u;
        const float* okp = g_outer + j * 256 + 128 + tc;
        float4 k0 = *(const float4*)okp;
        float4 k1 = *(const float4*)(okp + 4);
        float4 o0, o1;
        o0.x = acc[u][0] + s_bo[tc + 0] + k0.x;
        o0.y = acc[u][1] + s_bo[tc + 1] + k0.y;
        o0.z = acc[u][2] + s_bo[tc + 2] + k0.z;
        o0.w = acc[u][3] + s_bo[tc + 3] + k0.w;
        o1.x = acc[u][4] + s_bo[tc + 4] + k1.x;
        o1.y = acc[u][5] + s_bo[tc + 5] + k1.y;
        o1.z = acc[u][6] + s_bo[tc + 6] + k1.z;
        o1.w = acc[u][7] + s_bo[tc + 7] + k1.w;
        float* op = out + ((((size_t)i << 10) + j) << 7) + tc;
        *(float4*)op = o0;
        *((float4*)op + 1) = o1;
    }
}

// ---------------------------------------------------------------------------
extern "C" void kernel_launch(void* const* d_in, const int* in_sizes, int n_in,
                              void* d_out, int out_size)
{
    (void)in_sizes; (void)n_in; (void)out_size;
    const float* single        = (const float*)d_in[0];
    const float* rel_pos_feats = (const float*)d_in[1];
    const float* w_qk          = (const float*)d_in[2];
    const float* w_outer       = (const float*)d_in[3];
    const float* w_pair        = (const float*)d_in[4];
    const float* b_pair        = (const float*)d_in[5];
    const float* w_rel         = (const float*)d_in[6];
    const float* b_rel         = (const float*)d_in[7];
    const float* qk_bias       = (const float*)d_in[8];
    float* out = (float*)d_out;

    pool_gelu_kernel<<<1024, 768>>>(single);
    wmma_gemm<<<dim3(64, 8, 1), 256>>>(0, w_qk, nullptr, nullptr);       // qk
    wmma_gemm<<<dim3(32, 8, 1), 256>>>(1, rel_pos_feats, w_rel, b_rel);  // rel_enc
    sgemm_outer_splitk<<<dim3(2, 8, 6), 256>>>(w_outer);
    reduce_outer<<<1024, 256>>>();
    bias_vec<<<128, 256>>>(qk_bias);
    wmma_gemm<<<dim3(8, 8, 32), 256>>>(3, nullptr, nullptr, nullptr);    // t_q
    wmma_gemm<<<dim3(8, 8, 32), 256>>>(4, nullptr, nullptr, nullptr);    // t_k
    wmma_gemm<<<dim3(8, 8, 32), 256>>>(5, nullptr, nullptr, nullptr);    // sim
    transpose_t<<<dim3(16, 1024, 2), 256>>>();
    final_kernel<<<dim3(16, 1024, 1), 256>>>(w_pair, b_pair, out);
}